// round 15
// baseline (speedup 1.0000x reference)
#include <cuda_runtime.h>
#include <math.h>

#define B_ 128
#define S_ 1024
#define I_ 512
#define H_ 1024
#define O_ 512
#define WPITCH 1028      // W smem row pitch (floats): conflict-free broadcast reads

static __device__ float    g_xpT[(size_t)S_ * H_ * B_];  // [s][h][b]
static __device__ float    g_h[2 * H_ * B_];             // [buf][k][b]
static __device__ unsigned g_flag[4][32];                // monotonic per-producer flags

// ---------------------------------------------------------------------------
// Phase 1: xpT[s][h][b] = sum_i x[b][s][i]*W_ih[h][i] + b_ih[h] + b_hh[h]
// ---------------------------------------------------------------------------
__global__ void __launch_bounds__(256) xpT_gemm(const float* __restrict__ x,
                                                const float* __restrict__ W_ih,
                                                const float* __restrict__ b_ih,
                                                const float* __restrict__ b_hh) {
    __shared__ float As[2][8][132];
    __shared__ float Bs[2][8][132];
    const int s    = blockIdx.y;
    const int h0   = blockIdx.x * 128;
    const int tid  = threadIdx.x;
    const int row  = tid >> 1;
    const int iseg = (tid & 1) << 2;
    const int tx   = tid & 15;
    const int ty   = tid >> 4;

    const float* Ag = W_ih + (size_t)(h0 + row) * I_ + iseg;
    const float* Bg = x + ((size_t)row * S_ + s) * I_ + iseg;

    float acc[8][8];
#pragma unroll
    for (int u = 0; u < 8; u++)
#pragma unroll
        for (int v = 0; v < 8; v++) acc[u][v] = 0.f;

    float4 ra = *(const float4*)Ag;
    float4 rb = *(const float4*)Bg;
    int cur = 0;

    for (int ic = 0; ic < I_; ic += 8) {
        As[cur][iseg + 0][row] = ra.x; As[cur][iseg + 1][row] = ra.y;
        As[cur][iseg + 2][row] = ra.z; As[cur][iseg + 3][row] = ra.w;
        Bs[cur][iseg + 0][row] = rb.x; Bs[cur][iseg + 1][row] = rb.y;
        Bs[cur][iseg + 2][row] = rb.z; Bs[cur][iseg + 3][row] = rb.w;
        __syncthreads();
        if (ic + 8 < I_) {
            ra = *(const float4*)(Ag + ic + 8);
            rb = *(const float4*)(Bg + ic + 8);
        }
#pragma unroll
        for (int i = 0; i < 8; i++) {
            float a[8], b[8];
            *(float4*)&a[0] = *(const float4*)&As[cur][i][ty * 8];
            *(float4*)&a[4] = *(const float4*)&As[cur][i][ty * 8 + 4];
            *(float4*)&b[0] = *(const float4*)&Bs[cur][i][tx * 8];
            *(float4*)&b[4] = *(const float4*)&Bs[cur][i][tx * 8 + 4];
#pragma unroll
            for (int u = 0; u < 8; u++)
#pragma unroll
                for (int v = 0; v < 8; v++)
                    acc[u][v] = fmaf(a[u], b[v], acc[u][v]);
        }
        cur ^= 1;
    }
#pragma unroll
    for (int u = 0; u < 8; u++) {
        const int h = h0 + ty * 8 + u;
        const float bias = __ldg(&b_ih[h]) + __ldg(&b_hh[h]);
        float* dst = g_xpT + ((size_t)s * H_ + h) * B_ + tx * 8;
        float4 o0 = {acc[u][0] + bias, acc[u][1] + bias, acc[u][2] + bias, acc[u][3] + bias};
        float4 o1 = {acc[u][4] + bias, acc[u][5] + bias, acc[u][6] + bias, acc[u][7] + bias};
        *(float4*)dst = o0;
        *(float4*)(dst + 4) = o1;
    }
}

// Poll all 32 producer flags of this group (lane j -> flag j). Acquire load
// synchronizes-with the producers' (bar + fence + atomicAdd) release chain.
// Returns ballot of "flag >= target" (wrap-safe signed compare).
__device__ __forceinline__ unsigned poll32(const unsigned* fl, unsigned target) {
    unsigned f;
    asm volatile("ld.global.acquire.gpu.u32 %0, [%1];"
                 : "=r"(f) : "l"(fl + (threadIdx.x & 31)) : "memory");
    return __ballot_sync(0xffffffffu, (int)(f - target) >= 0);
}

// ---------------------------------------------------------------------------
// Phase 2: persistent scan, 128 CTAs x 128 threads. CTA c: gi=c>>5 (batch
// block of 32), jt=c&31 (32 output rows). Sync = per-producer monotonic flags;
// chunks consumed in rotated order starting at this CTA's own chunk, so
// straggler wait overlaps with compute instead of serializing.
// ---------------------------------------------------------------------------
__global__ void __launch_bounds__(128, 1) rnn_scan(const float* __restrict__ W_hh) {
    extern __shared__ float sm[];
    float* Wsm = sm;                      // [32][WPITCH]
    float* hs  = sm + 32 * WPITCH;        // [64][32]

    const int tid  = threadIdx.x;
    const int c    = blockIdx.x;
    const int gi   = c >> 5;
    const int jt   = c & 31;
    const int j0   = jt << 5;
    const int b0   = gi << 5;
    const int w    = tid >> 5;
    const int lane = tid & 31;
    const int jp   = lane >> 3;
    const int bq   = lane & 7;
    const int jA   = (w << 3) + (jp << 1);
    const int jgA  = j0 + jA;

    const unsigned* fl = g_flag[gi];
    unsigned base;
    asm volatile("ld.global.acquire.gpu.u32 %0, [%1];"
                 : "=r"(base) : "l"(&g_flag[gi][jt]) : "memory");

    {   // W_hh rows j0..j0+31 -> pitched smem (once)
        for (int r = w; r < 32; r += 4) {
            const float4* src = (const float4*)(W_hh + (size_t)(j0 + r) * H_);
            float4* dst = (float4*)(Wsm + r * WPITCH);
            for (int i = lane; i < H_ / 4; i += 32) dst[i] = src[i];
        }
    }
    {   // zero own h rows in buf0 ("produce h^0")
        const int kz = jt << 5;
        for (int i = tid; i < 1024; i += 128)
            g_h[(size_t)(kz + (i >> 5)) * B_ + b0 + (i & 31)] = 0.f;
    }
    __syncthreads();
    if (tid == 0) { __threadfence(); atomicAdd(&g_flag[gi][jt], 1u); }

    const float* wAp = Wsm + (size_t)jA * WPITCH;
    const float* wBp = wAp + WPITCH;
    const int hsoff = bq << 2;
    const int k0s = tid >> 3;             // staging k row 0..15 (+16/32/48)
    const int c0s = tid & 7;              // staging f4 col 0..7
    const int myc = jt >> 1;              // own chunk (contains own rows)

    for (int t = 0; t < S_; ++t) {
        const unsigned target = base + 1u + (unsigned)t;
        float*        hout = g_h + (size_t)((t + 1) & 1) * (H_ * B_);
        const float4* hin4 = (const float4*)(g_h + (size_t)(t & 1) * (H_ * B_)) + (b0 >> 2);

        const float* xpp = g_xpT + ((size_t)t * H_ + jgA) * B_ + b0 + hsoff;
        const float4 xa = __ldg((const float4*)xpp);
        const float4 xb = __ldg((const float4*)(xpp + B_));

        float4 aA = {0.f, 0.f, 0.f, 0.f};
        float4 aB = {0.f, 0.f, 0.f, 0.f};

        unsigned mask = poll32(fl, target);
        int ch = myc;
        while (((mask >> (ch << 1)) & 3u) != 3u) mask = poll32(fl, target);
        const float4* cb = hin4 + (size_t)ch * 64 * 32;
        float4 p0 = __ldcg(cb + (size_t)(k0s)      * 32 + c0s);
        float4 p1 = __ldcg(cb + (size_t)(k0s + 16) * 32 + c0s);
        float4 p2 = __ldcg(cb + (size_t)(k0s + 32) * 32 + c0s);
        float4 p3 = __ldcg(cb + (size_t)(k0s + 48) * 32 + c0s);

        for (int i = 0; i < 16; ++i) {
            __syncthreads();
            float4* hs4 = (float4*)hs;
            hs4[(k0s)      * 8 + c0s] = p0;
            hs4[(k0s + 16) * 8 + c0s] = p1;
            hs4[(k0s + 32) * 8 + c0s] = p2;
            hs4[(k0s + 48) * 8 + c0s] = p3;
            const int cur = ch;
            if (i < 15) {
                ch = (ch + 1) & 15;
                while (((mask >> (ch << 1)) & 3u) != 3u) mask = poll32(fl, target);
                const float4* nb = hin4 + (size_t)ch * 64 * 32;
                p0 = __ldcg(nb + (size_t)(k0s)      * 32 + c0s);
                p1 = __ldcg(nb + (size_t)(k0s + 16) * 32 + c0s);
                p2 = __ldcg(nb + (size_t)(k0s + 32) * 32 + c0s);
                p3 = __ldcg(nb + (size_t)(k0s + 48) * 32 + c0s);
            }
            __syncthreads();
            const float* wA = wAp + (cur << 6);
            const float* wB = wBp + (cur << 6);
#pragma unroll
            for (int k = 0; k < 64; k += 4) {
                const float4 wa = *(const float4*)(wA + k);
                const float4 wb = *(const float4*)(wB + k);
                const float* hp = hs + (k << 5) + hsoff;
                const float4 h0 = *(const float4*)(hp);
                const float4 h1 = *(const float4*)(hp + 32);
                const float4 h2 = *(const float4*)(hp + 64);
                const float4 h3 = *(const float4*)(hp + 96);
                aA.x = fmaf(wa.x, h0.x, aA.x); aA.y = fmaf(wa.x, h0.y, aA.y);
                aA.z = fmaf(wa.x, h0.z, aA.z); aA.w = fmaf(wa.x, h0.w, aA.w);
                aB.x = fmaf(wb.x, h0.x, aB.x); aB.y = fmaf(wb.x, h0.y, aB.y);
                aB.z = fmaf(wb.x, h0.z, aB.z); aB.w = fmaf(wb.x, h0.w, aB.w);
                aA.x = fmaf(wa.y, h1.x, aA.x); aA.y = fmaf(wa.y, h1.y, aA.y);
                aA.z = fmaf(wa.y, h1.z, aA.z); aA.w = fmaf(wa.y, h1.w, aA.w);
                aB.x = fmaf(wb.y, h1.x, aB.x); aB.y = fmaf(wb.y, h1.y, aB.y);
                aB.z = fmaf(wb.y, h1.z, aB.z); aB.w = fmaf(wb.y, h1.w, aB.w);
                aA.x = fmaf(wa.z, h2.x, aA.x); aA.y = fmaf(wa.z, h2.y, aA.y);
                aA.z = fmaf(wa.z, h2.z, aA.z); aA.w = fmaf(wa.z, h2.w, aA.w);
                aB.x = fmaf(wb.z, h2.x, aB.x); aB.y = fmaf(wb.z, h2.y, aB.y);
                aB.z = fmaf(wb.z, h2.z, aB.z); aB.w = fmaf(wb.z, h2.w, aB.w);
                aA.x = fmaf(wa.w, h3.x, aA.x); aA.y = fmaf(wa.w, h3.y, aA.y);
                aA.z = fmaf(wa.w, h3.z, aA.z); aA.w = fmaf(wa.w, h3.w, aA.w);
                aB.x = fmaf(wb.w, h3.x, aB.x); aB.y = fmaf(wb.w, h3.y, aB.y);
                aB.z = fmaf(wb.w, h3.z, aB.z); aB.w = fmaf(wb.w, h3.w, aB.w);
            }
        }
        float4 oA, oB;
        oA.x = tanhf(aA.x + xa.x); oA.y = tanhf(aA.y + xa.y);
        oA.z = tanhf(aA.z + xa.z); oA.w = tanhf(aA.w + xa.w);
        oB.x = tanhf(aB.x + xb.x); oB.y = tanhf(aB.y + xb.y);
        oB.z = tanhf(aB.z + xb.z); oB.w = tanhf(aB.w + xb.w);
        float* dA = hout + (size_t)jgA * B_ + b0 + hsoff;
        *(float4*)dA        = oA;
        *(float4*)(dA + B_) = oB;

        __syncthreads();                            // all CTA stores issued
        if (tid == 0) { __threadfence(); atomicAdd(&g_flag[gi][jt], 1u); }  // release h^{t+1}
    }
}

// ---------------------------------------------------------------------------
// Phase 3: out[b][o] = sum_k hT[k][b]*W_fc[o][k] + b_fc[o].  hT = g_h buf0.
// ---------------------------------------------------------------------------
__global__ void __launch_bounds__(128) fc_kernel(const float* __restrict__ W_fc,
                                                 const float* __restrict__ b_fc,
                                                 float* __restrict__ out) {
    const int o = blockIdx.x;
    const int b = threadIdx.x;
    const float* h = g_h;   // buf 0 (S even)
    const float* wr = W_fc + (size_t)o * H_;
    float s = 0.f;
#pragma unroll 4
    for (int k = 0; k < H_; k += 4) {
        const float4 wv = __ldg((const float4*)(wr + k));
        s = fmaf(wv.x, h[(size_t)(k + 0) * B_ + b], s);
        s = fmaf(wv.y, h[(size_t)(k + 1) * B_ + b], s);
        s = fmaf(wv.z, h[(size_t)(k + 2) * B_ + b], s);
        s = fmaf(wv.w, h[(size_t)(k + 3) * B_ + b], s);
    }
    out[(size_t)b * O_ + o] = s + __ldg(&b_fc[o]);
}

extern "C" void kernel_launch(void* const* d_in, const int* in_sizes, int n_in,
                              void* d_out, int out_size) {
    const float* x    = (const float*)d_in[0];
    const float* W_ih = (const float*)d_in[1];
    const float* W_hh = (const float*)d_in[2];
    const float* b_ih = (const float*)d_in[3];
    const float* b_hh = (const float*)d_in[4];
    const float* W_fc = (const float*)d_in[5];
    const float* b_fc = (const float*)d_in[6];
    float* out = (float*)d_out;

    xpT_gemm<<<dim3(8, 1024), 256>>>(x, W_ih, b_ih, b_hh);

    const int smem2 = (32 * WPITCH + 64 * 32) * (int)sizeof(float);
    cudaFuncSetAttribute(rnn_scan, cudaFuncAttributeMaxDynamicSharedMemorySize, smem2);
    rnn_scan<<<128, 128, smem2>>>(W_hh);

    fc_kernel<<<O_, B_>>>(W_fc, b_fc, out);
}

// round 17
// speedup vs baseline: 1.1149x; 1.1149x over previous
#include <cuda_runtime.h>
#include <math.h>

#define B_ 128
#define S_ 1024
#define I_ 512
#define H_ 1024
#define O_ 512
#define WPITCH 1028      // W smem row pitch (floats): conflict-free broadcast reads

static __device__ float    g_xpT[(size_t)S_ * H_ * B_];  // [s][h][b]
static __device__ float    g_h[2 * H_ * B_];             // [buf][k][b]
static __device__ unsigned g_tick[4];                    // monotonic ticket barriers

// ---------------------------------------------------------------------------
// Phase 1: xpT[s][h][b] = sum_i x[b][s][i]*W_ih[h][i] + b_ih[h] + b_hh[h]
// (unchanged from R14)
// ---------------------------------------------------------------------------
__global__ void __launch_bounds__(256) xpT_gemm(const float* __restrict__ x,
                                                const float* __restrict__ W_ih,
                                                const float* __restrict__ b_ih,
                                                const float* __restrict__ b_hh) {
    __shared__ float As[2][8][132];
    __shared__ float Bs[2][8][132];
    const int s    = blockIdx.y;
    const int h0   = blockIdx.x * 128;
    const int tid  = threadIdx.x;
    const int row  = tid >> 1;
    const int iseg = (tid & 1) << 2;
    const int tx   = tid & 15;
    const int ty   = tid >> 4;

    const float* Ag = W_ih + (size_t)(h0 + row) * I_ + iseg;
    const float* Bg = x + ((size_t)row * S_ + s) * I_ + iseg;

    float acc[8][8];
#pragma unroll
    for (int u = 0; u < 8; u++)
#pragma unroll
        for (int v = 0; v < 8; v++) acc[u][v] = 0.f;

    float4 ra = *(const float4*)Ag;
    float4 rb = *(const float4*)Bg;
    int cur = 0;

    for (int ic = 0; ic < I_; ic += 8) {
        As[cur][iseg + 0][row] = ra.x; As[cur][iseg + 1][row] = ra.y;
        As[cur][iseg + 2][row] = ra.z; As[cur][iseg + 3][row] = ra.w;
        Bs[cur][iseg + 0][row] = rb.x; Bs[cur][iseg + 1][row] = rb.y;
        Bs[cur][iseg + 2][row] = rb.z; Bs[cur][iseg + 3][row] = rb.w;
        __syncthreads();
        if (ic + 8 < I_) {
            ra = *(const float4*)(Ag + ic + 8);
            rb = *(const float4*)(Bg + ic + 8);
        }
#pragma unroll
        for (int i = 0; i < 8; i++) {
            float a[8], b[8];
            *(float4*)&a[0] = *(const float4*)&As[cur][i][ty * 8];
            *(float4*)&a[4] = *(const float4*)&As[cur][i][ty * 8 + 4];
            *(float4*)&b[0] = *(const float4*)&Bs[cur][i][tx * 8];
            *(float4*)&b[4] = *(const float4*)&Bs[cur][i][tx * 8 + 4];
#pragma unroll
            for (int u = 0; u < 8; u++)
#pragma unroll
                for (int v = 0; v < 8; v++)
                    acc[u][v] = fmaf(a[u], b[v], acc[u][v]);
        }
        cur ^= 1;
    }
#pragma unroll
    for (int u = 0; u < 8; u++) {
        const int h = h0 + ty * 8 + u;
        const float bias = __ldg(&b_ih[h]) + __ldg(&b_hh[h]);
        float* dst = g_xpT + ((size_t)s * H_ + h) * B_ + tx * 8;
        float4 o0 = {acc[u][0] + bias, acc[u][1] + bias, acc[u][2] + bias, acc[u][3] + bias};
        float4 o1 = {acc[u][4] + bias, acc[u][5] + bias, acc[u][6] + bias, acc[u][7] + bias};
        *(float4*)dst = o0;
        *(float4*)(dst + 4) = o1;
    }
}

// ---------------------------------------------------------------------------
// Ticket barrier among 32 CTAs of one batch group (verbatim from R14: proven).
// Monotonic counter: no reset, correct across graph replays.
// ---------------------------------------------------------------------------
__device__ __forceinline__ void group_barrier(unsigned* t) {
    __threadfence();
    __syncthreads();
    if (threadIdx.x == 0) {
        const unsigned my = atomicAdd(t, 1u);
        const unsigned target = ((my >> 5) + 1u) << 5;   // 32 arrivals/generation
        volatile unsigned* vt = t;
        while (*vt < target) { }
        __threadfence();
    }
    __syncthreads();
}

// ---------------------------------------------------------------------------
// Phase 2: persistent scan, 128 CTAs x 256 threads (2 warps/SMSP).
// CTA c: gi=c>>5 (batch block of 32), jt=c&31 (32 output rows).
// Warp w (0..7), lane: jp=lane>>3, bq=lane&7. Thread: 1 j-row x 4 b.
//   j = j0 + w*4 + jp,  b = b0 + bq*4.
// Per 4-k per thread: 1 W LDS.128 (4-addr broadcast) + 4 h LDS.128 + 16 FMA.
// h staged through double-buffered smem: store -> ONE sync -> compute;
// next-chunk LDG prefetch issued right after the sync (overlaps compute).
// ---------------------------------------------------------------------------
__global__ void __launch_bounds__(256, 1) rnn_scan(const float* __restrict__ W_hh) {
    extern __shared__ float sm[];
    float* Wsm = sm;                      // [32][WPITCH]
    float* hs  = sm + 32 * WPITCH;        // [2][64][32]

    const int tid  = threadIdx.x;
    const int c    = blockIdx.x;
    const int gi   = c >> 5;
    const int jt   = c & 31;
    const int j0   = jt << 5;
    const int b0   = gi << 5;
    const int w    = tid >> 5;
    const int lane = tid & 31;
    const int jp   = lane >> 3;           // 0..3
    const int bq   = lane & 7;            // 0..7
    const int jl   = (w << 2) + jp;       // 0..31
    const int jg   = j0 + jl;

    {   // W_hh rows j0..j0+31 -> pitched smem (once); warp w: rows w, w+8, ...
        for (int r = w; r < 32; r += 8) {
            const float4* src = (const float4*)(W_hh + (size_t)(j0 + r) * H_);
            float4* dst = (float4*)(Wsm + r * WPITCH);
            for (int i = lane; i < H_ / 4; i += 32) dst[i] = src[i];
        }
    }
    {   // zero own h rows in buf0
        const int kz = jt << 5;
        for (int i = tid; i < 1024; i += 256)
            g_h[(size_t)(kz + (i >> 5)) * B_ + b0 + (i & 31)] = 0.f;
    }
    group_barrier(&g_tick[gi]);

    const float* wp  = Wsm + (size_t)jl * WPITCH;
    const int    sk  = tid >> 3;          // staging k row 0..31 (+32)
    const int    sc  = tid & 7;           // staging f4 col 0..7
    const int    hoff = bq << 2;

    for (int t = 0; t < S_; ++t) {
        float*        hout = g_h + (size_t)((t + 1) & 1) * (H_ * B_);
        const float4* hin4 = (const float4*)(g_h + (size_t)(t & 1) * (H_ * B_)) + (b0 >> 2);

        const float4 xv = __ldg((const float4*)(g_xpT + ((size_t)t * H_ + jg) * B_ + b0 + hoff));

        float4 aA = {0.f, 0.f, 0.f, 0.f};

        float4 p0 = hin4[(size_t)sk        * 32 + sc];
        float4 p1 = hin4[(size_t)(sk + 32) * 32 + sc];

        for (int ch = 0; ch < 16; ++ch) {
            float4* dst = (float4*)hs + (ch & 1) * 512;
            dst[sk * 8 + sc]        = p0;
            dst[(sk + 32) * 8 + sc] = p1;
            __syncthreads();
            if (ch < 15) {
                const float4* nb = hin4 + (size_t)(ch + 1) * 64 * 32;
                p0 = nb[(size_t)sk        * 32 + sc];
                p1 = nb[(size_t)(sk + 32) * 32 + sc];
            }
            const float* hb = hs + (ch & 1) * 2048;
            const float* wA = wp + (ch << 6);
#pragma unroll
            for (int k = 0; k < 64; k += 4) {
                const float4 wa = *(const float4*)(wA + k);
                const float* hp = hb + (k << 5) + hoff;
                const float4 h0 = *(const float4*)(hp);
                const float4 h1 = *(const float4*)(hp + 32);
                const float4 h2 = *(const float4*)(hp + 64);
                const float4 h3 = *(const float4*)(hp + 96);
                aA.x = fmaf(wa.x, h0.x, aA.x); aA.y = fmaf(wa.x, h0.y, aA.y);
                aA.z = fmaf(wa.x, h0.z, aA.z); aA.w = fmaf(wa.x, h0.w, aA.w);
                aA.x = fmaf(wa.y, h1.x, aA.x); aA.y = fmaf(wa.y, h1.y, aA.y);
                aA.z = fmaf(wa.y, h1.z, aA.z); aA.w = fmaf(wa.y, h1.w, aA.w);
                aA.x = fmaf(wa.z, h2.x, aA.x); aA.y = fmaf(wa.z, h2.y, aA.y);
                aA.z = fmaf(wa.z, h2.z, aA.z); aA.w = fmaf(wa.z, h2.w, aA.w);
                aA.x = fmaf(wa.w, h3.x, aA.x); aA.y = fmaf(wa.w, h3.y, aA.y);
                aA.z = fmaf(wa.w, h3.z, aA.z); aA.w = fmaf(wa.w, h3.w, aA.w);
            }
        }
        float4 oA;
        oA.x = tanhf(aA.x + xv.x); oA.y = tanhf(aA.y + xv.y);
        oA.z = tanhf(aA.z + xv.z); oA.w = tanhf(aA.w + xv.w);
        *(float4*)(hout + (size_t)jg * B_ + b0 + hoff) = oA;

        group_barrier(&g_tick[gi]);
    }
}

// ---------------------------------------------------------------------------
// Phase 3: out[b][o] = sum_k hT[k][b]*W_fc[o][k] + b_fc[o].  hT = g_h buf0.
// ---------------------------------------------------------------------------
__global__ void __launch_bounds__(128) fc_kernel(const float* __restrict__ W_fc,
                                                 const float* __restrict__ b_fc,
                                                 float* __restrict__ out) {
    const int o = blockIdx.x;
    const int b = threadIdx.x;
    const float* h = g_h;   // buf 0 (S even)
    const float* wr = W_fc + (size_t)o * H_;
    float s = 0.f;
#pragma unroll 4
    for (int k = 0; k < H_; k += 4) {
        const float4 wv = __ldg((const float4*)(wr + k));
        s = fmaf(wv.x, h[(size_t)(k + 0) * B_ + b], s);
        s = fmaf(wv.y, h[(size_t)(k + 1) * B_ + b], s);
        s = fmaf(wv.z, h[(size_t)(k + 2) * B_ + b], s);
        s = fmaf(wv.w, h[(size_t)(k + 3) * B_ + b], s);
    }
    out[(size_t)b * O_ + o] = s + __ldg(&b_fc[o]);
}

extern "C" void kernel_launch(void* const* d_in, const int* in_sizes, int n_in,
                              void* d_out, int out_size) {
    const float* x    = (const float*)d_in[0];
    const float* W_ih = (const float*)d_in[1];
    const float* W_hh = (const float*)d_in[2];
    const float* b_ih = (const float*)d_in[3];
    const float* b_hh = (const float*)d_in[4];
    const float* W_fc = (const float*)d_in[5];
    const float* b_fc = (const float*)d_in[6];
    float* out = (float*)d_out;

    xpT_gemm<<<dim3(8, 1024), 256>>>(x, W_ih, b_ih, b_hh);

    const int smem2 = (32 * WPITCH + 2 * 64 * 32) * (int)sizeof(float);
    cudaFuncSetAttribute(rnn_scan, cudaFuncAttributeMaxDynamicSharedMemorySize, smem2);
    rnn_scan<<<128, 256, smem2>>>(W_hh);

    fc_kernel<<<O_, B_>>>(W_fc, b_fc, out);
}